// round 13
// baseline (speedup 1.0000x reference)
#include <cuda_runtime.h>
#include <cuda_fp16.h>
#include <cstdint>
#include <math.h>

// Problem constants
#define Bc2  2
#define Sc   2048
#define Dc   1024
#define Hc   16
#define DKc  64
#define Mc   (Bc2*Sc)

#define L2E 1.4426950408889634f

// Persistent scheduler constants
#define NCTAS   296
#define N_QKV   768
#define N_ATTN  512
#define N_OUT   256
#define N_ITEMS 1536
#define CONSUME 1832u   // N_ITEMS + NCTAS (exact per-launch queue consumption)

// Scratch (allocation-free rule: __device__ globals)
__device__ __half g_inh[3u*Mc*Dc];       // q,k,v inputs as fp16
__device__ __half g_wh[4u*Dc*Dc];        // Wq,Wk,Wv,Wo as fp16
__device__ __half g_Q[Bc2*Hc*Sc*DKc];    // [B,H,S,DK]
__device__ __half g_K[Bc2*Hc*Sc*DKc];
__device__ __half g_V[Bc2*Hc*Sc*DKc];
__device__ __half g_ctx[Bc2*Sc*Dc];      // merged-head [B,S,D]

// Scheduler state (zero-initialized at module load; never reset — epoch-based)
__device__ unsigned long long g_ticket;          // CTA tickets (epoch derivation)
__device__ unsigned long long g_item;            // work-queue head (monotonic)
__device__ unsigned int g_qk[3*2*8*32];          // [(z,b,nt)] * 32-word pad
__device__ unsigned int g_cc[2*16*32];           // [(b,qb)]   * 32-word pad

// ---------------------------------------------------------------------------
// helpers
// ---------------------------------------------------------------------------
__device__ __forceinline__ uint32_t packh2(float lo, float hi) {
    __half2 h = __floats2half2_rn(lo, hi);
    return *(uint32_t*)&h;
}
__device__ __forceinline__ uint32_t smem_u32(const void* p) {
    uint32_t a;
    asm("{ .reg .u64 t; cvta.to.shared.u64 t, %1; cvt.u32.u64 %0, t; }"
        : "=r"(a) : "l"(p));
    return a;
}
__device__ __forceinline__ float ex2f(float x) {
    float r;
    asm("ex2.approx.ftz.f32 %0, %1;" : "=f"(r) : "f"(x));
    return r;
}
__device__ __forceinline__ uint32_t h2ex2(float x0, float x1) {
    __half2 h = __floats2half2_rn(x0, x1);
    uint32_t hi = *(uint32_t*)&h, r;
    asm("ex2.approx.f16x2 %0, %1;" : "=r"(r) : "r"(hi));
    return r;
}
__device__ __forceinline__ void mma16(float c[4], const uint32_t a[4],
                                      uint32_t b0, uint32_t b1) {
    asm volatile(
        "mma.sync.aligned.m16n8k16.row.col.f32.f16.f16.f32 "
        "{%0,%1,%2,%3},{%4,%5,%6,%7},{%8,%9},{%0,%1,%2,%3};"
        : "+f"(c[0]), "+f"(c[1]), "+f"(c[2]), "+f"(c[3])
        : "r"(a[0]), "r"(a[1]), "r"(a[2]), "r"(a[3]), "r"(b0), "r"(b1));
}
#define LDMX4(r0, r1, r2, r3, addr) \
    asm volatile("ldmatrix.sync.aligned.m8n8.x4.shared.b16 {%0,%1,%2,%3}, [%4];" \
                 : "=r"(r0), "=r"(r1), "=r"(r2), "=r"(r3) : "r"(addr))
#define LDMX4T(r0, r1, r2, r3, addr) \
    asm volatile("ldmatrix.sync.aligned.m8n8.x4.trans.shared.b16 {%0,%1,%2,%3}, [%4];" \
                 : "=r"(r0), "=r"(r1), "=r"(r2), "=r"(r3) : "r"(addr))
#define CP16(dst, src) \
    asm volatile("cp.async.cg.shared.global [%0], [%1], 16;" \
                 :: "r"(dst), "l"(src) : "memory")
#define CP_COMMIT() asm volatile("cp.async.commit_group;" ::: "memory")
#define CP_WAIT0()  asm volatile("cp.async.wait_group 0;" ::: "memory")
#define CP_WAIT1()  asm volatile("cp.async.wait_group 1;" ::: "memory")

__device__ __forceinline__ unsigned int ld_acq(const unsigned int* p) {
    unsigned int v;
    asm volatile("ld.acquire.gpu.global.u32 %0, [%1];" : "=r"(v) : "l"(p));
    return v;
}
__device__ __forceinline__ void red_rel(unsigned int* p) {
    asm volatile("red.release.gpu.global.add.u32 [%0], 1;" :: "l"(p) : "memory");
}
__device__ __forceinline__ void spin_wait(const unsigned int* p, unsigned int tgt) {
    while (ld_acq(p) < tgt) {
        asm volatile("nanosleep.u32 128;");
    }
}

// ===========================================================================
// fp32 -> fp16 conversion pass (query,key,value, Wq,Wk,Wv,Wo)
// ===========================================================================
__global__ __launch_bounds__(256) void cvt_fp16(
    const float* __restrict__ q, const float* __restrict__ k, const float* __restrict__ v,
    const float* __restrict__ wq, const float* __restrict__ wk,
    const float* __restrict__ wv, const float* __restrict__ wo,
    __half* __restrict__ inh, __half* __restrict__ wh)
{
    const int y = blockIdx.y;
    const float* src;
    __half* dst;
    int n;
    if (y < 3) {
        src = (y == 0) ? q : (y == 1) ? k : v;
        dst = inh + (size_t)y * Mc * Dc;
        n = Mc * Dc;
    } else {
        const int w = y - 3;
        src = (w == 0) ? wq : (w == 1) ? wk : (w == 2) ? wv : wo;
        dst = wh + (size_t)w * Dc * Dc;
        n = Dc * Dc;
    }
    const int n4 = n >> 2;
    for (int i = blockIdx.x * 256 + threadIdx.x; i < n4; i += gridDim.x * 256) {
        float4 f = ((const float4*)src)[i];
        uint2 u;
        u.x = packh2(f.x, f.y);
        u.y = packh2(f.z, f.w);
        ((uint2*)dst)[i] = u;
    }
}

// ===========================================================================
// fp16 GEMM item (R7 body, parameterized): C = A @ W^T + bias, tile 128x128,
// 8 warps (2m x 4n), k-chunk 64, 2-stage cp.async, 64 KB dynamic smem.
// ===========================================================================
#define MSTG 16384u
#define GEMM_DYN_SMEM 65536u

__device__ __noinline__ void hgemm_item(
    const __half* __restrict__ A, const __half* __restrict__ W,
    const float* __restrict__ bias, __half* __restrict__ Ch,
    float* __restrict__ Cf, int split_head, int m0, int n0,
    uint32_t* dynsm)
{
    const int tid  = threadIdx.x;
    const int lane = tid & 31;
    const int wid  = tid >> 5;
    const int wm   = wid & 1;
    const int wn   = wid >> 1;
    const int g    = lane >> 2;
    const int t    = lane & 3;

    const uint32_t sA0 = smem_u32(dynsm);
    const uint32_t sB0 = sA0 + 2 * MSTG;

    float acc[4][4][4];
#pragma unroll
    for (int mi = 0; mi < 4; mi++)
#pragma unroll
        for (int nj = 0; nj < 4; nj++)
#pragma unroll
            for (int r = 0; r < 4; r++) acc[mi][nj][r] = 0.f;

    int rw[4], sg[4];
    uint32_t dOf[4];
#pragma unroll
    for (int i = 0; i < 4; i++) {
        const int s = tid + (i << 8);
        rw[i] = s >> 3;
        sg[i] = s & 7;
        dOf[i] = (uint32_t)(rw[i] * 128 + ((sg[i] ^ (rw[i] & 7)) << 4));
    }

#pragma unroll
    for (int i = 0; i < 4; i++) {
        CP16(sA0 + dOf[i], A + (size_t)(m0 + rw[i]) * Dc + sg[i] * 8);
        CP16(sB0 + dOf[i], W + (size_t)(n0 + rw[i]) * Dc + sg[i] * 8);
    }
    CP_COMMIT();

    const int laneq = lane & 15;
    const int rmg   = laneq & 7;
    const int cbit  = lane >> 4;
    uint32_t aRow[4], bRow[2];
#pragma unroll
    for (int mi = 0; mi < 4; mi++)
        aRow[mi] = sA0 + (wm * 64 + mi * 16 + laneq) * 128;
#pragma unroll
    for (int njp = 0; njp < 2; njp++)
        bRow[njp] = sB0 + (wn * 32 + njp * 16 + laneq) * 128;

    for (int kc = 0; kc < 16; kc++) {
        CP_WAIT0();
        __syncthreads();
        if (kc < 15) {
            const int k0 = (kc + 1) << 6;
            const uint32_t so = ((kc + 1) & 1) * MSTG;
#pragma unroll
            for (int i = 0; i < 4; i++) {
                CP16(sA0 + so + dOf[i], A + (size_t)(m0 + rw[i]) * Dc + k0 + sg[i] * 8);
                CP16(sB0 + so + dOf[i], W + (size_t)(n0 + rw[i]) * Dc + k0 + sg[i] * 8);
            }
        }
        CP_COMMIT();

        const uint32_t so = (kc & 1) * MSTG;
#pragma unroll
        for (int kt = 0; kt < 4; kt++) {
            const uint32_t c16 = (uint32_t)(((2 * kt + cbit) ^ rmg) << 4);
            uint32_t af[4][4];
#pragma unroll
            for (int mi = 0; mi < 4; mi++)
                LDMX4(af[mi][0], af[mi][1], af[mi][2], af[mi][3],
                      aRow[mi] + so + c16);
#pragma unroll
            for (int njp = 0; njp < 2; njp++) {
                uint32_t b0, b1, b2, b3;
                LDMX4(b0, b1, b2, b3, bRow[njp] + so + c16);
#pragma unroll
                for (int mi = 0; mi < 4; mi++) {
                    mma16(acc[mi][2 * njp],     af[mi], b0, b2);
                    mma16(acc[mi][2 * njp + 1], af[mi], b1, b3);
                }
            }
        }
    }
    CP_WAIT0();

#pragma unroll
    for (int nj = 0; nj < 4; nj++) {
        const int col = n0 + wn * 32 + nj * 8 + (t << 1);
        const float bx = bias[col], by = bias[col + 1];
#pragma unroll
        for (int mi = 0; mi < 4; mi++) {
            const int r1 = m0 + wm * 64 + mi * 16 + g;
            const int r2 = r1 + 8;
            if (split_head) {
                const int h = col >> 6, d = col & (DKc - 1);
                const int b1_ = r1 >> 11, s1 = r1 & (Sc - 1);
                const int b2_ = r2 >> 11, s2 = r2 & (Sc - 1);
                __half2 lo = __floats2half2_rn(acc[mi][nj][0] + bx, acc[mi][nj][1] + by);
                __half2 hi = __floats2half2_rn(acc[mi][nj][2] + bx, acc[mi][nj][3] + by);
                *(__half2*)(Ch + ((size_t)(b1_ * Hc + h) * Sc + s1) * DKc + d) = lo;
                *(__half2*)(Ch + ((size_t)(b2_ * Hc + h) * Sc + s2) * DKc + d) = hi;
            } else {
                float2 lo = make_float2(acc[mi][nj][0] + bx, acc[mi][nj][1] + by);
                float2 hi = make_float2(acc[mi][nj][2] + bx, acc[mi][nj][3] + by);
                *(float2*)(Cf + (size_t)r1 * Dc + col) = lo;
                *(float2*)(Cf + (size_t)r2 * Dc + col) = hi;
            }
        }
    }
}

// ===========================================================================
// Flash attention item (R7 body, parameterized): 128 q-rows of one (b,h),
// fp16 mma, base-2 softmax via f16x2 MUFU, 3-stage cp.async ring (48 KB).
// ===========================================================================
#define ASTGB 8192u

__device__ __noinline__ void attn_item(
    const __half* __restrict__ Q, const __half* __restrict__ K,
    const __half* __restrict__ V, __half* __restrict__ ctx,
    int bh, int q0, uint32_t* dynsm)
{
    const int tid  = threadIdx.x;
    const int lane = tid & 31;
    const int wid  = tid >> 5;
    const int g    = lane >> 2;
    const int t    = lane & 3;

    const __half* Qb = Q + (size_t)bh * Sc * DKc;
    const __half* Kb = K + (size_t)bh * Sc * DKc;
    const __half* Vb = V + (size_t)bh * Sc * DKc;

    const uint32_t sK0 = smem_u32(dynsm);
    const uint32_t sV0 = sK0 + 3 * 64 * 32 * 4;   // +24576

    const int r_lo = q0 + wid * 16 + g;
    const int r_hi = r_lo + 8;

    uint32_t qa[4][4];
    {
        const __half2 sc2 = __float2half2_rn(0.125f);
#pragma unroll
        for (int kt = 0; kt < 4; kt++) {
            const int d0 = kt * 16 + 2 * t;
            __half2 a0 = __hmul2(*(const __half2*)(Qb + (size_t)r_lo * DKc + d0), sc2);
            __half2 a1 = __hmul2(*(const __half2*)(Qb + (size_t)r_hi * DKc + d0), sc2);
            __half2 a2 = __hmul2(*(const __half2*)(Qb + (size_t)r_lo * DKc + d0 + 8), sc2);
            __half2 a3 = __hmul2(*(const __half2*)(Qb + (size_t)r_hi * DKc + d0 + 8), sc2);
            qa[kt][0] = *(uint32_t*)&a0; qa[kt][1] = *(uint32_t*)&a1;
            qa[kt][2] = *(uint32_t*)&a2; qa[kt][3] = *(uint32_t*)&a3;
        }
    }

    const int row0 = tid >> 3,         ch0 = tid & 7;
    const int row1 = (tid + 256) >> 3, ch1 = (tid + 256) & 7;
    const uint32_t o0 = (uint32_t)(row0 * 128 + ((ch0 ^ (row0 & 7)) << 4));
    const uint32_t o1 = (uint32_t)(row1 * 128 + ((ch1 ^ (row1 & 7)) << 4));
    const __half* gK0 = Kb + (size_t)row0 * DKc + ch0 * 8;
    const __half* gK1 = Kb + (size_t)row1 * DKc + ch1 * 8;
    const __half* gV0 = Vb + (size_t)row0 * DKc + ch0 * 8;
    const __half* gV1 = Vb + (size_t)row1 * DKc + ch1 * 8;

    const int laneq = lane & 15;
    const int swz   = lane & 7;
    const int cbit  = lane >> 4;
    const uint32_t krow = (uint32_t)laneq * 128;
    const uint32_t vrow = (uint32_t)((lane & 7) + ((lane >> 3) & 1) * 8) * 128;

    float O[8][4];
#pragma unroll
    for (int jd = 0; jd < 8; jd++)
#pragma unroll
        for (int r = 0; r < 4; r++) O[jd][r] = 0.f;
    float m_lo = -1e30f, m_hi = -1e30f, l_lo = 0.f, l_hi = 0.f;

#pragma unroll
    for (int st = 0; st < 2; st++) {
        const uint32_t so = st * ASTGB;
        const size_t goff = (size_t)(st << 6) * DKc;
        CP16(sK0 + so + o0, gK0 + goff); CP16(sK0 + so + o1, gK1 + goff);
        CP16(sV0 + so + o0, gV0 + goff); CP16(sV0 + so + o1, gV1 + goff);
        CP_COMMIT();
    }

    for (int it = 0; it < Sc / 64; it++) {
        CP_WAIT1();
        __syncthreads();
        if (it + 2 < Sc / 64) {
            const int kv2 = (it + 2) << 6;
            const uint32_t so = ((it + 2) % 3) * ASTGB;
            const size_t goff = (size_t)kv2 * DKc;
            CP16(sK0 + so + o0, gK0 + goff); CP16(sK0 + so + o1, gK1 + goff);
            CP16(sV0 + so + o0, gV0 + goff); CP16(sV0 + so + o1, gV1 + goff);
        }
        CP_COMMIT();

        const uint32_t so = (it % 3) * ASTGB;

        float sc[8][4];
#pragma unroll
        for (int j = 0; j < 8; j++)
#pragma unroll
            for (int r = 0; r < 4; r++) sc[j][r] = 0.f;
#pragma unroll
        for (int kt = 0; kt < 4; kt++) {
            const uint32_t c16 = (uint32_t)(((kt * 2 + cbit) ^ swz) << 4);
#pragma unroll
            for (int jp = 0; jp < 4; jp++) {
                uint32_t b0, b1, b2, b3;
                LDMX4(b0, b1, b2, b3, sK0 + so + (uint32_t)(jp * 2048) + krow + c16);
                mma16(sc[2 * jp],     qa[kt], b0, b2);
                mma16(sc[2 * jp + 1], qa[kt], b1, b3);
            }
        }

        float mx_lo = -1e30f, mx_hi = -1e30f;
#pragma unroll
        for (int j = 0; j < 8; j++) {
            mx_lo = fmaxf(mx_lo, fmaxf(sc[j][0], sc[j][1]));
            mx_hi = fmaxf(mx_hi, fmaxf(sc[j][2], sc[j][3]));
        }
        mx_lo = fmaxf(mx_lo, __shfl_xor_sync(0xffffffffu, mx_lo, 1));
        mx_lo = fmaxf(mx_lo, __shfl_xor_sync(0xffffffffu, mx_lo, 2));
        mx_hi = fmaxf(mx_hi, __shfl_xor_sync(0xffffffffu, mx_hi, 1));
        mx_hi = fmaxf(mx_hi, __shfl_xor_sync(0xffffffffu, mx_hi, 2));

        const float mn_lo = fmaxf(m_lo, mx_lo);
        const float mn_hi = fmaxf(m_hi, mx_hi);
        const float f_lo  = ex2f((m_lo - mn_lo) * L2E);
        const float f_hi  = ex2f((m_hi - mn_hi) * L2E);
        m_lo = mn_lo; m_hi = mn_hi;
        const float c_lo = mn_lo * L2E;
        const float c_hi = mn_hi * L2E;

        float rs_lo = 0.f, rs_hi = 0.f;
        uint32_t pLo[8], pHi[8];
#pragma unroll
        for (int j = 0; j < 8; j++) {
            const float x0 = fmaf(sc[j][0], L2E, -c_lo);
            const float x1 = fmaf(sc[j][1], L2E, -c_lo);
            pLo[j] = h2ex2(x0, x1);
            __half2 ph = *(__half2*)&pLo[j];
            float2 pf2 = __half22float2(ph);
            rs_lo += pf2.x + pf2.y;

            const float y0 = fmaf(sc[j][2], L2E, -c_hi);
            const float y1 = fmaf(sc[j][3], L2E, -c_hi);
            pHi[j] = h2ex2(y0, y1);
            __half2 qh = *(__half2*)&pHi[j];
            float2 qf2 = __half22float2(qh);
            rs_hi += qf2.x + qf2.y;
        }
        rs_lo += __shfl_xor_sync(0xffffffffu, rs_lo, 1);
        rs_lo += __shfl_xor_sync(0xffffffffu, rs_lo, 2);
        rs_hi += __shfl_xor_sync(0xffffffffu, rs_hi, 1);
        rs_hi += __shfl_xor_sync(0xffffffffu, rs_hi, 2);
        l_lo = l_lo * f_lo + rs_lo;
        l_hi = l_hi * f_hi + rs_hi;

#pragma unroll
        for (int jd = 0; jd < 8; jd++) {
            O[jd][0] *= f_lo; O[jd][1] *= f_lo;
            O[jd][2] *= f_hi; O[jd][3] *= f_hi;
        }

#pragma unroll
        for (int u = 0; u < 4; u++) {
            uint32_t pf[4];
            pf[0] = pLo[2*u];
            pf[1] = pHi[2*u];
            pf[2] = pLo[2*u + 1];
            pf[3] = pHi[2*u + 1];
#pragma unroll
            for (int cg = 0; cg < 4; cg++) {
                const uint32_t c16 = (uint32_t)(((cg * 2 + cbit) ^ swz) << 4);
                uint32_t d0, d1, d2, d3;
                LDMX4T(d0, d1, d2, d3, sV0 + so + (uint32_t)(u * 2048) + vrow + c16);
                mma16(O[2*cg],     pf, d0, d1);
                mma16(O[2*cg + 1], pf, d2, d3);
            }
        }
    }
    CP_WAIT0();

    const float inv_lo = 1.f / l_lo;
    const float inv_hi = 1.f / l_hi;
    const int b = bh >> 4, h = bh & (Hc - 1);
#pragma unroll
    for (int jd = 0; jd < 8; jd++) {
        const int col = h * DKc + jd * 8 + (t << 1);
        __half2 lo = __floats2half2_rn(O[jd][0] * inv_lo, O[jd][1] * inv_lo);
        __half2 hi = __floats2half2_rn(O[jd][2] * inv_hi, O[jd][3] * inv_hi);
        *(__half2*)(ctx + (size_t)(b * Sc + r_lo) * Dc + col) = lo;
        *(__half2*)(ctx + (size_t)(b * Sc + r_hi) * Dc + col) = hi;
    }
}

// ===========================================================================
// Persistent mega-kernel: dynamic work-stealing over topologically-ordered
// items (768 qkv -> 512 attn -> 256 out) with epoch-based release/acquire
// gating. Exactly NCTAS CTAs, all co-resident (2/SM).
// ===========================================================================
__global__ __launch_bounds__(256, 2) void mega(
    const __half* __restrict__ inh, const __half* __restrict__ wh,
    const float* __restrict__ bq, const float* __restrict__ bk,
    const float* __restrict__ bv, const float* __restrict__ bo,
    __half* __restrict__ Qo, __half* __restrict__ Ko, __half* __restrict__ Vo,
    __half* __restrict__ ctxb, float* __restrict__ out)
{
    extern __shared__ uint32_t dynsm[];
    __shared__ unsigned int sEpoch;
    __shared__ unsigned int sRel;

    const int tid = threadIdx.x;
    if (tid == 0) {
        unsigned long long tk = atomicAdd(&g_ticket, 1ULL);
        sEpoch = (unsigned int)(tk / NCTAS) + 1u;
    }
    __syncthreads();
    const unsigned int E = sEpoch;
    const unsigned long long base = (unsigned long long)(E - 1) * CONSUME;
    const unsigned int tgt = 16u * E;

    for (;;) {
        __syncthreads();                 // smem reuse guard between items
        if (tid == 0) {
            unsigned long long gidx = atomicAdd(&g_item, 1ULL);
            sRel = (unsigned int)(gidx - base);
        }
        __syncthreads();
        const unsigned int rel = sRel;
        if (rel >= N_ITEMS) break;       // exactly one overshoot grab per CTA

        if (rel < N_QKV) {
            // ---- QKV projection tile ----
            const int z  = rel >> 8;
            const int mt = (rel & 255) >> 3;
            const int nt = rel & 7;
            const __half* A = inh + (size_t)z * Mc * Dc;
            const __half* W = wh + (size_t)z * Dc * Dc;
            const float* bias = (z == 0) ? bq : (z == 1) ? bk : bv;
            __half* C = (z == 0) ? Qo : (z == 1) ? Ko : Vo;
            hgemm_item(A, W, bias, C, nullptr, 1, mt << 7, nt << 7, dynsm);
            __threadfence();
            __syncthreads();
            if (tid == 0)
                red_rel(&g_qk[(((z * 2) + (mt >> 4)) * 8 + nt) * 32]);
        } else if (rel < N_QKV + N_ATTN) {
            // ---- attention tile ----
            const int a  = (int)rel - N_QKV;
            const int bh = a >> 4;
            const int qb = a & 15;
            const int b  = bh >> 4;
            const int nt = (bh & 15) >> 1;
            if (tid == 0) {
                spin_wait(&g_qk[((0 * 2 + b) * 8 + nt) * 32], tgt);
                spin_wait(&g_qk[((1 * 2 + b) * 8 + nt) * 32], tgt);
                spin_wait(&g_qk[((2 * 2 + b) * 8 + nt) * 32], tgt);
            }
            __syncthreads();
            attn_item(Qo, Ko, Vo, ctxb, bh, qb << 7, dynsm);
            __threadfence();
            __syncthreads();
            if (tid == 0)
                red_rel(&g_cc[((b * 16) + qb) * 32]);
        } else {
            // ---- output projection tile ----
            const int o  = (int)rel - (N_QKV + N_ATTN);
            const int mt = o >> 3;
            const int nt = o & 7;
            const int b  = mt >> 4;
            const int qb = mt & 15;
            if (tid == 0)
                spin_wait(&g_cc[((b * 16) + qb) * 32], tgt);
            __syncthreads();
            hgemm_item(ctxb, wh + (size_t)3 * Dc * Dc, bo, nullptr, out, 0,
                       mt << 7, nt << 7, dynsm);
        }
    }
}

// ---------------------------------------------------------------------------
// Launch
// ---------------------------------------------------------------------------
extern "C" void kernel_launch(void* const* d_in, const int* in_sizes, int n_in,
                              void* d_out, int out_size)
{
    const float* query = (const float*)d_in[0];
    const float* key   = (const float*)d_in[1];
    const float* value = (const float*)d_in[2];
    const float* Wq    = (const float*)d_in[3];
    const float* bq    = (const float*)d_in[4];
    const float* Wk    = (const float*)d_in[5];
    const float* bk    = (const float*)d_in[6];
    const float* Wv    = (const float*)d_in[7];
    const float* bv    = (const float*)d_in[8];
    const float* Wo    = (const float*)d_in[9];
    const float* bo    = (const float*)d_in[10];
    float* out = (float*)d_out;

    __half *inh, *wh, *qbuf, *kbuf, *vbuf, *cbuf;
    cudaGetSymbolAddress((void**)&inh,  g_inh);
    cudaGetSymbolAddress((void**)&wh,   g_wh);
    cudaGetSymbolAddress((void**)&qbuf, g_Q);
    cudaGetSymbolAddress((void**)&kbuf, g_K);
    cudaGetSymbolAddress((void**)&vbuf, g_V);
    cudaGetSymbolAddress((void**)&cbuf, g_ctx);

    cudaFuncSetAttribute(mega, cudaFuncAttributeMaxDynamicSharedMemorySize,
                         GEMM_DYN_SMEM);

    cvt_fp16<<<dim3(256, 7), 256>>>(query, key, value, Wq, Wk, Wv, Wo, inh, wh);

    mega<<<NCTAS, 256, GEMM_DYN_SMEM>>>(inh, wh, bq, bk, bv, bo,
                                        qbuf, kbuf, vbuf, cbuf, out);
}

// round 14
// speedup vs baseline: 1.1980x; 1.1980x over previous
#include <cuda_runtime.h>
#include <cuda_fp16.h>
#include <cstdint>
#include <math.h>

// Problem constants
#define Bc2  2
#define Sc   2048
#define Dc   1024
#define Hc   16
#define DKc  64
#define Mc   (Bc2*Sc)

#define L2E 1.4426950408889634f

// Scratch (allocation-free rule: __device__ globals)
__device__ __half g_inh[3u*Mc*Dc];       // q,k,v inputs as fp16
__device__ __half g_wh[4u*Dc*Dc];        // Wq,Wk,Wv,Wo as fp16
__device__ __half g_Q[Bc2*Hc*Sc*DKc];    // [B,H,S,DK]
__device__ __half g_K[Bc2*Hc*Sc*DKc];
__device__ __half g_V[Bc2*Hc*Sc*DKc];
__device__ __half g_ctx[Bc2*Sc*Dc];      // merged-head [B,S,D]

// ---------------------------------------------------------------------------
// helpers
// ---------------------------------------------------------------------------
__device__ __forceinline__ uint32_t packh2(float lo, float hi) {
    __half2 h = __floats2half2_rn(lo, hi);
    return *(uint32_t*)&h;
}
__device__ __forceinline__ uint32_t smem_u32(const void* p) {
    uint32_t a;
    asm("{ .reg .u64 t; cvta.to.shared.u64 t, %1; cvt.u32.u64 %0, t; }"
        : "=r"(a) : "l"(p));
    return a;
}
__device__ __forceinline__ float ex2f(float x) {
    float r;
    asm("ex2.approx.ftz.f32 %0, %1;" : "=f"(r) : "f"(x));
    return r;
}
// one MUFU op -> two fp16 exp2 results (already the packed P pair)
__device__ __forceinline__ uint32_t h2ex2(float x0, float x1) {
    __half2 h = __floats2half2_rn(x0, x1);
    uint32_t hi = *(uint32_t*)&h, r;
    asm("ex2.approx.f16x2 %0, %1;" : "=r"(r) : "r"(hi));
    return r;
}
__device__ __forceinline__ void mma16(float c[4], const uint32_t a[4],
                                      uint32_t b0, uint32_t b1) {
    asm volatile(
        "mma.sync.aligned.m16n8k16.row.col.f32.f16.f16.f32 "
        "{%0,%1,%2,%3},{%4,%5,%6,%7},{%8,%9},{%0,%1,%2,%3};"
        : "+f"(c[0]), "+f"(c[1]), "+f"(c[2]), "+f"(c[3])
        : "r"(a[0]), "r"(a[1]), "r"(a[2]), "r"(a[3]), "r"(b0), "r"(b1));
}
#define LDMX4(r0, r1, r2, r3, addr) \
    asm volatile("ldmatrix.sync.aligned.m8n8.x4.shared.b16 {%0,%1,%2,%3}, [%4];" \
                 : "=r"(r0), "=r"(r1), "=r"(r2), "=r"(r3) : "r"(addr))
#define LDMX4T(r0, r1, r2, r3, addr) \
    asm volatile("ldmatrix.sync.aligned.m8n8.x4.trans.shared.b16 {%0,%1,%2,%3}, [%4];" \
                 : "=r"(r0), "=r"(r1), "=r"(r2), "=r"(r3) : "r"(addr))
#define CP16(dst, src) \
    asm volatile("cp.async.cg.shared.global [%0], [%1], 16;" \
                 :: "r"(dst), "l"(src) : "memory")
#define CP_COMMIT() asm volatile("cp.async.commit_group;" ::: "memory")
#define CP_WAIT0()  asm volatile("cp.async.wait_group 0;" ::: "memory")
#define CP_WAIT1()  asm volatile("cp.async.wait_group 1;" ::: "memory")

// ===========================================================================
// fp32 -> fp16 conversion pass (query,key,value, Wq,Wk,Wv,Wo)
// ===========================================================================
__global__ __launch_bounds__(256) void cvt_fp16(
    const float* __restrict__ q, const float* __restrict__ k, const float* __restrict__ v,
    const float* __restrict__ wq, const float* __restrict__ wk,
    const float* __restrict__ wv, const float* __restrict__ wo,
    __half* __restrict__ inh, __half* __restrict__ wh)
{
    const int y = blockIdx.y;
    const float* src;
    __half* dst;
    int n;
    if (y < 3) {
        src = (y == 0) ? q : (y == 1) ? k : v;
        dst = inh + (size_t)y * Mc * Dc;
        n = Mc * Dc;
    } else {
        const int w = y - 3;
        src = (w == 0) ? wq : (w == 1) ? wk : (w == 2) ? wv : wo;
        dst = wh + (size_t)w * Dc * Dc;
        n = Dc * Dc;
    }
    const int n4 = n >> 2;
    for (int i = blockIdx.x * 256 + threadIdx.x; i < n4; i += gridDim.x * 256) {
        float4 f = ((const float4*)src)[i];
        uint2 u;
        u.x = packh2(f.x, f.y);
        u.y = packh2(f.z, f.w);
        ((uint2*)dst)[i] = u;
    }
}

// ===========================================================================
// fp16 GEMM: C = A @ W^T + bias. CTA 128x128, 8 warps (2m x 4n, warp 64x32),
// k-chunk 64, 2-stage cp.async in 64 KB DYNAMIC smem,
// SW128-style swizzle (seg ^= row&7), ldmatrix.x4.   (R7 — proven best)
// ===========================================================================
#define MSTG 16384u   // bytes per matrix-stage (128 rows x 128 B)
#define GEMM_DYN_SMEM (4u * MSTG)   // 64 KB

__device__ __forceinline__ void hgemm_body(
    const __half* __restrict__ A, const __half* __restrict__ W,
    const float* __restrict__ bias, __half* __restrict__ Ch,
    float* __restrict__ Cf, int split_head)
{
    extern __shared__ uint32_t dynsm[];   // A s0, A s1, B s0, B s1

    const int tid  = threadIdx.x;
    const int lane = tid & 31;
    const int wid  = tid >> 5;
    const int wm   = wid & 1;
    const int wn   = wid >> 1;
    const int g    = lane >> 2;
    const int t    = lane & 3;
    const int m0   = blockIdx.y << 7;
    const int n0   = blockIdx.x << 7;

    const uint32_t sA0 = smem_u32(dynsm);
    const uint32_t sB0 = sA0 + 2 * MSTG;

    float acc[4][4][4];
#pragma unroll
    for (int mi = 0; mi < 4; mi++)
#pragma unroll
        for (int nj = 0; nj < 4; nj++)
#pragma unroll
            for (int r = 0; r < 4; r++) acc[mi][nj][r] = 0.f;

    // cp.async staging: 1024 16B-segments per matrix-stage, 4 per thread
    int rw[4], sg[4];
    uint32_t dOf[4];
#pragma unroll
    for (int i = 0; i < 4; i++) {
        const int s = tid + (i << 8);
        rw[i] = s >> 3;
        sg[i] = s & 7;
        dOf[i] = (uint32_t)(rw[i] * 128 + ((sg[i] ^ (rw[i] & 7)) << 4));
    }

    // prologue: stage chunk 0
#pragma unroll
    for (int i = 0; i < 4; i++) {
        CP16(sA0 + dOf[i], A + (size_t)(m0 + rw[i]) * Dc + sg[i] * 8);
        CP16(sB0 + dOf[i], W + (size_t)(n0 + rw[i]) * Dc + sg[i] * 8);
    }
    CP_COMMIT();

    // fragment bases
    const int laneq = lane & 15;
    const int rmg   = laneq & 7;
    const int cbit  = lane >> 4;
    uint32_t aRow[4], bRow[2];
#pragma unroll
    for (int mi = 0; mi < 4; mi++)
        aRow[mi] = sA0 + (wm * 64 + mi * 16 + laneq) * 128;
#pragma unroll
    for (int njp = 0; njp < 2; njp++)
        bRow[njp] = sB0 + (wn * 32 + njp * 16 + laneq) * 128;

    for (int kc = 0; kc < 16; kc++) {
        CP_WAIT0();
        __syncthreads();
        if (kc < 15) {
            const int k0 = (kc + 1) << 6;
            const uint32_t so = ((kc + 1) & 1) * MSTG;
#pragma unroll
            for (int i = 0; i < 4; i++) {
                CP16(sA0 + so + dOf[i], A + (size_t)(m0 + rw[i]) * Dc + k0 + sg[i] * 8);
                CP16(sB0 + so + dOf[i], W + (size_t)(n0 + rw[i]) * Dc + k0 + sg[i] * 8);
            }
        }
        CP_COMMIT();

        const uint32_t so = (kc & 1) * MSTG;
#pragma unroll
        for (int kt = 0; kt < 4; kt++) {
            const uint32_t c16 = (uint32_t)(((2 * kt + cbit) ^ rmg) << 4);
            uint32_t af[4][4];
#pragma unroll
            for (int mi = 0; mi < 4; mi++)
                LDMX4(af[mi][0], af[mi][1], af[mi][2], af[mi][3],
                      aRow[mi] + so + c16);
#pragma unroll
            for (int njp = 0; njp < 2; njp++) {
                uint32_t b0, b1, b2, b3;
                LDMX4(b0, b1, b2, b3, bRow[njp] + so + c16);
#pragma unroll
                for (int mi = 0; mi < 4; mi++) {
                    mma16(acc[mi][2 * njp],     af[mi], b0, b2);
                    mma16(acc[mi][2 * njp + 1], af[mi], b1, b3);
                }
            }
        }
    }

    // epilogue
#pragma unroll
    for (int nj = 0; nj < 4; nj++) {
        const int col = n0 + wn * 32 + nj * 8 + (t << 1);
        const float bx = bias[col], by = bias[col + 1];
#pragma unroll
        for (int mi = 0; mi < 4; mi++) {
            const int r1 = m0 + wm * 64 + mi * 16 + g;
            const int r2 = r1 + 8;
            if (split_head) {
                const int h = col >> 6, d = col & (DKc - 1);
                const int b1_ = r1 >> 11, s1 = r1 & (Sc - 1);
                const int b2_ = r2 >> 11, s2 = r2 & (Sc - 1);
                __half2 lo = __floats2half2_rn(acc[mi][nj][0] + bx, acc[mi][nj][1] + by);
                __half2 hi = __floats2half2_rn(acc[mi][nj][2] + bx, acc[mi][nj][3] + by);
                *(__half2*)(Ch + ((size_t)(b1_ * Hc + h) * Sc + s1) * DKc + d) = lo;
                *(__half2*)(Ch + ((size_t)(b2_ * Hc + h) * Sc + s2) * DKc + d) = hi;
            } else {
                float2 lo = make_float2(acc[mi][nj][0] + bx, acc[mi][nj][1] + by);
                float2 hi = make_float2(acc[mi][nj][2] + bx, acc[mi][nj][3] + by);
                *(float2*)(Cf + (size_t)r1 * Dc + col) = lo;
                *(float2*)(Cf + (size_t)r2 * Dc + col) = hi;
            }
        }
    }
}

__global__ __launch_bounds__(256, 2) void qkv_gemm(
    const __half* __restrict__ inh, const __half* __restrict__ wh,
    const float* __restrict__ bq, const float* __restrict__ bk,
    const float* __restrict__ bv,
    __half* __restrict__ Qo, __half* __restrict__ Ko, __half* __restrict__ Vo)
{
    const int z = blockIdx.z;
    const __half* A = inh + (size_t)z * Mc * Dc;
    const __half* W = wh + (size_t)z * Dc * Dc;
    const float* b  = (z == 0) ? bq : (z == 1) ? bk : bv;
    __half* C = (z == 0) ? Qo : (z == 1) ? Ko : Vo;
    hgemm_body(A, W, b, C, nullptr, 1);
}

__global__ __launch_bounds__(256, 2) void out_gemm(
    const __half* __restrict__ A, const __half* __restrict__ wh,
    const float* __restrict__ bias, float* __restrict__ C)
{
    hgemm_body(A, wh + (size_t)3 * Dc * Dc, bias, nullptr, C, 0);
}

// ===========================================================================
// Flash attention, fp16 mma m16n8k16, 4 warps x 32 q-rows (two m16 bands):
// each K/V ldmatrix.x4 now feeds 4 MMAs (2 bands x 2) -> smem crossbar
// traffic per output row HALVED vs the 8-warp/16-row layout.
// Base-2 softmax with f16x2 MUFU, 3-stage cp.async K/V ring (48 KB static).
// ===========================================================================
#define ASTGB 8192u          // bytes per matrix-stage (64 rows x 128 B)

__global__ __launch_bounds__(128, 2) void attn_mma(
    const __half* __restrict__ Q, const __half* __restrict__ K,
    const __half* __restrict__ V, __half* __restrict__ ctx)
{
    __shared__ uint32_t sK[3 * 64 * 32];   // 24 KB
    __shared__ uint32_t sV[3 * 64 * 32];   // 24 KB

    const int tid  = threadIdx.x;          // 0..127
    const int lane = tid & 31;
    const int wid  = tid >> 5;             // 0..3
    const int g    = lane >> 2;
    const int t    = lane & 3;
    const int bh   = blockIdx.y;
    const int q0   = blockIdx.x << 7;

    const __half* Qb = Q + (size_t)bh * Sc * DKc;
    const __half* Kb = K + (size_t)bh * Sc * DKc;
    const __half* Vb = V + (size_t)bh * Sc * DKc;

    const uint32_t sK0 = smem_u32(sK);
    const uint32_t sV0 = smem_u32(sV);

    // two 16-row bands per warp
    int rlo[2], rhi[2];
#pragma unroll
    for (int b = 0; b < 2; b++) {
        rlo[b] = q0 + wid * 32 + b * 16 + g;
        rhi[b] = rlo[b] + 8;
    }

    // Q A-frags, scale = 1/8 (exact)
    uint32_t qa[2][4][4];
    {
        const __half2 sc2 = __float2half2_rn(0.125f);
#pragma unroll
        for (int b = 0; b < 2; b++)
#pragma unroll
            for (int kt = 0; kt < 4; kt++) {
                const int d0 = kt * 16 + 2 * t;
                __half2 a0 = __hmul2(*(const __half2*)(Qb + (size_t)rlo[b] * DKc + d0), sc2);
                __half2 a1 = __hmul2(*(const __half2*)(Qb + (size_t)rhi[b] * DKc + d0), sc2);
                __half2 a2 = __hmul2(*(const __half2*)(Qb + (size_t)rlo[b] * DKc + d0 + 8), sc2);
                __half2 a3 = __hmul2(*(const __half2*)(Qb + (size_t)rhi[b] * DKc + d0 + 8), sc2);
                qa[b][kt][0] = *(uint32_t*)&a0; qa[b][kt][1] = *(uint32_t*)&a1;
                qa[b][kt][2] = *(uint32_t*)&a2; qa[b][kt][3] = *(uint32_t*)&a3;
            }
    }

    // cp.async staging map: 512 segments per matrix-tile; 4 per thread
    int srow[4], sch[4];
    uint32_t so_[4];
#pragma unroll
    for (int i = 0; i < 4; i++) {
        const int s = tid + (i << 7);
        srow[i] = s >> 3;
        sch[i]  = s & 7;
        so_[i]  = (uint32_t)(srow[i] * 128 + ((sch[i] ^ (srow[i] & 7)) << 4));
    }

    // fragment addressing keys
    const int laneq = lane & 15;
    const int swz   = lane & 7;
    const int cbit  = lane >> 4;
    const uint32_t krow = (uint32_t)laneq * 128;
    const uint32_t vrow = (uint32_t)((lane & 7) + ((lane >> 3) & 1) * 8) * 128;

    float O[2][8][4];
#pragma unroll
    for (int b = 0; b < 2; b++)
#pragma unroll
        for (int jd = 0; jd < 8; jd++)
#pragma unroll
            for (int r = 0; r < 4; r++) O[b][jd][r] = 0.f;
    float m_lo[2] = {-1e30f, -1e30f}, m_hi[2] = {-1e30f, -1e30f};
    float l_lo[2] = {0.f, 0.f},       l_hi[2] = {0.f, 0.f};

    // prologue: stage tiles 0 and 1
#pragma unroll
    for (int st = 0; st < 2; st++) {
        const uint32_t so = st * ASTGB;
        const size_t goff = (size_t)(st << 6) * DKc;
#pragma unroll
        for (int i = 0; i < 4; i++) {
            CP16(sK0 + so + so_[i], Kb + goff + (size_t)srow[i] * DKc + sch[i] * 8);
            CP16(sV0 + so + so_[i], Vb + goff + (size_t)srow[i] * DKc + sch[i] * 8);
        }
        CP_COMMIT();
    }

    for (int it = 0; it < Sc / 64; it++) {
        CP_WAIT1();
        __syncthreads();
        if (it + 2 < Sc / 64) {
            const uint32_t so = ((it + 2) % 3) * ASTGB;
            const size_t goff = (size_t)((it + 2) << 6) * DKc;
#pragma unroll
            for (int i = 0; i < 4; i++) {
                CP16(sK0 + so + so_[i], Kb + goff + (size_t)srow[i] * DKc + sch[i] * 8);
                CP16(sV0 + so + so_[i], Vb + goff + (size_t)srow[i] * DKc + sch[i] * 8);
            }
        }
        CP_COMMIT();

        const uint32_t so = (it % 3) * ASTGB;

        // scores: both bands share every K fragment (4 MMAs per ldmatrix)
        float sc[2][8][4];
#pragma unroll
        for (int b = 0; b < 2; b++)
#pragma unroll
            for (int j = 0; j < 8; j++)
#pragma unroll
                for (int r = 0; r < 4; r++) sc[b][j][r] = 0.f;
#pragma unroll
        for (int kt = 0; kt < 4; kt++) {
            const uint32_t c16 = (uint32_t)(((kt * 2 + cbit) ^ swz) << 4);
#pragma unroll
            for (int jp = 0; jp < 4; jp++) {
                uint32_t b0, b1, b2, b3;
                LDMX4(b0, b1, b2, b3, sK0 + so + (uint32_t)(jp * 2048) + krow + c16);
                mma16(sc[0][2 * jp],     qa[0][kt], b0, b2);
                mma16(sc[0][2 * jp + 1], qa[0][kt], b1, b3);
                mma16(sc[1][2 * jp],     qa[1][kt], b0, b2);
                mma16(sc[1][2 * jp + 1], qa[1][kt], b1, b3);
            }
        }

        // online softmax per band (f16x2 MUFU path)
        uint32_t pLo[2][8], pHi[2][8];
        float fB_lo[2], fB_hi[2];
#pragma unroll
        for (int b = 0; b < 2; b++) {
            float mx_lo = -1e30f, mx_hi = -1e30f;
#pragma unroll
            for (int j = 0; j < 8; j++) {
                mx_lo = fmaxf(mx_lo, fmaxf(sc[b][j][0], sc[b][j][1]));
                mx_hi = fmaxf(mx_hi, fmaxf(sc[b][j][2], sc[b][j][3]));
            }
            mx_lo = fmaxf(mx_lo, __shfl_xor_sync(0xffffffffu, mx_lo, 1));
            mx_lo = fmaxf(mx_lo, __shfl_xor_sync(0xffffffffu, mx_lo, 2));
            mx_hi = fmaxf(mx_hi, __shfl_xor_sync(0xffffffffu, mx_hi, 1));
            mx_hi = fmaxf(mx_hi, __shfl_xor_sync(0xffffffffu, mx_hi, 2));

            const float mn_lo = fmaxf(m_lo[b], mx_lo);
            const float mn_hi = fmaxf(m_hi[b], mx_hi);
            fB_lo[b] = ex2f((m_lo[b] - mn_lo) * L2E);
            fB_hi[b] = ex2f((m_hi[b] - mn_hi) * L2E);
            m_lo[b] = mn_lo; m_hi[b] = mn_hi;
            const float c_lo = mn_lo * L2E;
            const float c_hi = mn_hi * L2E;

            float rs_lo = 0.f, rs_hi = 0.f;
#pragma unroll
            for (int j = 0; j < 8; j++) {
                pLo[b][j] = h2ex2(fmaf(sc[b][j][0], L2E, -c_lo),
                                  fmaf(sc[b][j][1], L2E, -c_lo));
                __half2 ph = *(__half2*)&pLo[b][j];
                float2 pf2 = __half22float2(ph);
                rs_lo += pf2.x + pf2.y;

                pHi[b][j] = h2ex2(fmaf(sc[b][j][2], L2E, -c_hi),
                                  fmaf(sc[b][j][3], L2E, -c_hi));
                __half2 qh = *(__half2*)&pHi[b][j];
                float2 qf2 = __half22float2(qh);
                rs_hi += qf2.x + qf2.y;
            }
            rs_lo += __shfl_xor_sync(0xffffffffu, rs_lo, 1);
            rs_lo += __shfl_xor_sync(0xffffffffu, rs_lo, 2);
            rs_hi += __shfl_xor_sync(0xffffffffu, rs_hi, 1);
            rs_hi += __shfl_xor_sync(0xffffffffu, rs_hi, 2);
            l_lo[b] = l_lo[b] * fB_lo[b] + rs_lo;
            l_hi[b] = l_hi[b] * fB_hi[b] + rs_hi;

#pragma unroll
            for (int jd = 0; jd < 8; jd++) {
                O[b][jd][0] *= fB_lo[b]; O[b][jd][1] *= fB_lo[b];
                O[b][jd][2] *= fB_hi[b]; O[b][jd][3] *= fB_hi[b];
            }
        }

        // PV: both bands share every V fragment (4 MMAs per ldmatrix)
#pragma unroll
        for (int u = 0; u < 4; u++) {
            uint32_t pf0[4], pf1[4];
            pf0[0] = pLo[0][2*u];     pf0[1] = pHi[0][2*u];
            pf0[2] = pLo[0][2*u + 1]; pf0[3] = pHi[0][2*u + 1];
            pf1[0] = pLo[1][2*u];     pf1[1] = pHi[1][2*u];
            pf1[2] = pLo[1][2*u + 1]; pf1[3] = pHi[1][2*u + 1];
#pragma unroll
            for (int cg = 0; cg < 4; cg++) {
                const uint32_t c16 = (uint32_t)(((cg * 2 + cbit) ^ swz) << 4);
                uint32_t d0, d1, d2, d3;
                LDMX4T(d0, d1, d2, d3, sV0 + so + (uint32_t)(u * 2048) + vrow + c16);
                mma16(O[0][2*cg],     pf0, d0, d1);
                mma16(O[0][2*cg + 1], pf0, d2, d3);
                mma16(O[1][2*cg],     pf1, d0, d1);
                mma16(O[1][2*cg + 1], pf1, d2, d3);
            }
        }
    }

    // epilogue: normalize, write merged-head ctx [B,S,D] fp16
    const int b_ = bh >> 4, h = bh & (Hc - 1);
#pragma unroll
    for (int b = 0; b < 2; b++) {
        const float inv_lo = 1.f / l_lo[b];
        const float inv_hi = 1.f / l_hi[b];
#pragma unroll
        for (int jd = 0; jd < 8; jd++) {
            const int col = h * DKc + jd * 8 + (t << 1);
            __half2 lo = __floats2half2_rn(O[b][jd][0] * inv_lo, O[b][jd][1] * inv_lo);
            __half2 hi = __floats2half2_rn(O[b][jd][2] * inv_hi, O[b][jd][3] * inv_hi);
            *(__half2*)(ctx + (size_t)(b_ * Sc + rlo[b]) * Dc + col) = lo;
            *(__half2*)(ctx + (size_t)(b_ * Sc + rhi[b]) * Dc + col) = hi;
        }
    }
}

// ---------------------------------------------------------------------------
// Launch
// ---------------------------------------------------------------------------
extern "C" void kernel_launch(void* const* d_in, const int* in_sizes, int n_in,
                              void* d_out, int out_size)
{
    const float* query = (const float*)d_in[0];
    const float* key   = (const float*)d_in[1];
    const float* value = (const float*)d_in[2];
    const float* Wq    = (const float*)d_in[3];
    const float* bq    = (const float*)d_in[4];
    const float* Wk    = (const float*)d_in[5];
    const float* bk    = (const float*)d_in[6];
    const float* Wv    = (const float*)d_in[7];
    const float* bv    = (const float*)d_in[8];
    const float* Wo    = (const float*)d_in[9];
    const float* bo    = (const float*)d_in[10];
    float* out = (float*)d_out;

    __half *inh, *wh, *qbuf, *kbuf, *vbuf, *cbuf;
    cudaGetSymbolAddress((void**)&inh,  g_inh);
    cudaGetSymbolAddress((void**)&wh,   g_wh);
    cudaGetSymbolAddress((void**)&qbuf, g_Q);
    cudaGetSymbolAddress((void**)&kbuf, g_K);
    cudaGetSymbolAddress((void**)&vbuf, g_V);
    cudaGetSymbolAddress((void**)&cbuf, g_ctx);

    // Function-attribute calls (not stream ops — graph-capture safe, idempotent)
    cudaFuncSetAttribute(qkv_gemm, cudaFuncAttributeMaxDynamicSharedMemorySize,
                         GEMM_DYN_SMEM);
    cudaFuncSetAttribute(out_gemm, cudaFuncAttributeMaxDynamicSharedMemorySize,
                         GEMM_DYN_SMEM);

    cvt_fp16<<<dim3(256, 7), 256>>>(query, key, value, Wq, Wk, Wv, Wo, inh, wh);

    dim3 qgrid(Dc / 128, Mc / 128, 3);   // (8, 32, 3)
    qkv_gemm<<<qgrid, 256, GEMM_DYN_SMEM>>>(inh, wh, bq, bk, bv, qbuf, kbuf, vbuf);

    dim3 agrid(Sc / 128, Bc2 * Hc);      // (16, 32)
    attn_mma<<<agrid, 128>>>(qbuf, kbuf, vbuf, cbuf);

    dim3 ogrid(Dc / 128, Mc / 128);      // (8, 32)
    out_gemm<<<ogrid, 256, GEMM_DYN_SMEM>>>(cbuf, wh, bo, out);
}